// round 15
// baseline (speedup 1.0000x reference)
#include <cuda_runtime.h>
#include <cuda_fp16.h>
#include <cstdint>

#define NNODE 50000
#define NEDGE 200000
#define NG    64
#define NF    1536
#define NH    1024
#define NC    80
#define NFUSE 1024
#define NCOMB (NF + NH)   // 2560
#define NSCANB 196        // ceil(NNODE/256)

// ---------------- scratch (device globals) ----------------------------------
__device__ __half  g_xh  [(size_t)NNODE * NF];      // x in fp16
__device__ __half  g_b1h [(size_t)NNODE * NH];      // gemm out / reuse
__device__ __half  g_b2h [(size_t)NNODE * NH];      // gather out
__device__ __half2 g_wp1 [(size_t)(NF / 2) * NH];   // W1 k-pair packed
__device__ __half2 g_wp2 [(size_t)(NH / 2) * NH];   // W2 k-pair packed
__device__ float g_dis  [NNODE];
__device__ float g_selfw[NNODE];
__device__ int   g_cnti [NNODE];
__device__ int   g_cur  [NNODE];
__device__ int   g_basev[NNODE + 1];
__device__ int   g_bsum [256];
__device__ int   g_csrs [NEDGE];
__device__ float g_csrw [NEDGE];
__device__ float g_pooled[NG * NH];
__device__ float g_cntg [NG];
__device__ float g_hid [NG * NFUSE];

// ---------------- helpers ----------------------------------------------------
__device__ __forceinline__ void mma_f16(float c[4], const uint32_t a[4],
                                        const uint32_t b[2]) {
    asm volatile(
        "mma.sync.aligned.m16n8k16.row.col.f32.f16.f16.f32 "
        "{%0,%1,%2,%3}, {%4,%5,%6,%7}, {%8,%9}, {%0,%1,%2,%3};"
        : "+f"(c[0]), "+f"(c[1]), "+f"(c[2]), "+f"(c[3])
        : "r"(a[0]), "r"(a[1]), "r"(a[2]), "r"(a[3]), "r"(b[0]), "r"(b[1]));
}

__device__ __forceinline__ void red_add_v4(float* p, float4 v) {
    asm volatile("red.add.v4.f32 [%0], {%1,%2,%3,%4};"
                 :: "l"(p), "f"(v.x), "f"(v.y), "f"(v.z), "f"(v.w) : "memory");
}

#define CP_ASYNC16(dst, src, sz) \
    asm volatile("cp.async.cg.shared.global [%0], [%1], 16, %2;" \
                 :: "r"(dst), "l"(src), "r"(sz) : "memory")
#define CP_COMMIT()  asm volatile("cp.async.commit_group;" ::: "memory")
#define CP_WAIT(n)   asm volatile("cp.async.wait_group %0;" :: "n"(n) : "memory")

// ---------------- fp16 mma.sync GEMM, BK=64 (R14, unchanged) ------------------
#define A_STRIDE 36
#define B_STRIDE 136
#define A_U32    (128 * A_STRIDE)          // 4608
#define B_U32    (32 * B_STRIDE)           // 4352
#define STAGE_U32 (A_U32 + B_U32)          // 8960
#define GEMM_SMEM (3 * STAGE_U32 * 4)      // 107520 B

__global__ __launch_bounds__(128, 2)
void gemm_h(const __half* __restrict__ A, const __half2* __restrict__ Wp,
            __half* __restrict__ C, int M, int K, int nChunk) {
    extern __shared__ uint32_t sm[];
    uint32_t smb;
    asm("{ .reg .u64 t; cvta.to.shared.u64 t, %1; cvt.u32.u64 %0, t; }"
        : "=r"(smb) : "l"(sm));

    const int tid  = threadIdx.x;
    const int lane = tid & 31;
    const int warp = tid >> 5;
    const int wm   = (warp & 1) * 64;
    const int wn   = (warp >> 1) * 64;
    const int grp  = lane >> 2;
    const int thr  = lane & 3;

    const int rowBase = blockIdx.y * 128;
    const int colBase = blockIdx.x * 128;

    auto issue = [&](int chunk, int st) {
        const uint32_t base = smb + (uint32_t)st * (STAGE_U32 * 4);
        const int k0  = chunk * 64;
        const int k02 = chunk * 32;
#pragma unroll
        for (int u = 0; u < 8; u++) {
            int t = tid + u * 128;
            int r = t >> 3, c = t & 7;
            uint32_t dst = base + (uint32_t)(r * A_STRIDE + c * 4) * 4u;
            int row = rowBase + r;
            int ok  = row < M;
            const __half* srcp = A + (size_t)(ok ? row : 0) * K + k0 + c * 8;
            CP_ASYNC16(dst, srcp, ok ? 16 : 0);
        }
#pragma unroll
        for (int u = 0; u < 8; u++) {
            int t = tid + u * 128;
            int k2 = t >> 5, c = t & 31;
            uint32_t dst = base + (uint32_t)(A_U32 + k2 * B_STRIDE + c * 4) * 4u;
            const __half2* srcp = Wp + (size_t)(k02 + k2) * NH + colBase + c * 4;
            CP_ASYNC16(dst, srcp, 16);
        }
    };

    float acc[4][8][4];
#pragma unroll
    for (int i = 0; i < 4; i++)
#pragma unroll
        for (int j = 0; j < 8; j++)
#pragma unroll
            for (int r = 0; r < 4; r++) acc[i][j][r] = 0.f;

    issue(0, 0); CP_COMMIT();
    issue(1, 1); CP_COMMIT();

    for (int i = 0; i < nChunk; i++) {
        const int si = i % 3;
        CP_WAIT(1);
        __syncthreads();

        const uint32_t* As = sm + si * STAGE_U32;
        const uint32_t* Bs = sm + si * STAGE_U32 + A_U32;

#pragma unroll
        for (int kk = 0; kk < 4; kk++) {
            const int kb2 = kk * 8;
            uint32_t af[4][4], bf[8][2];
#pragma unroll
            for (int mi = 0; mi < 4; mi++) {
                int m = wm + mi * 16 + grp;
                af[mi][0] = As[m * A_STRIDE + kb2 + thr];
                af[mi][1] = As[(m + 8) * A_STRIDE + kb2 + thr];
                af[mi][2] = As[m * A_STRIDE + kb2 + 4 + thr];
                af[mi][3] = As[(m + 8) * A_STRIDE + kb2 + 4 + thr];
            }
#pragma unroll
            for (int ni = 0; ni < 8; ni++) {
                int n = wn + ni * 8 + grp;
                bf[ni][0] = Bs[(kb2 + thr) * B_STRIDE + n];
                bf[ni][1] = Bs[(kb2 + 4 + thr) * B_STRIDE + n];
            }
#pragma unroll
            for (int mi = 0; mi < 4; mi++)
#pragma unroll
                for (int ni = 0; ni < 8; ni++)
                    mma_f16(acc[mi][ni], af[mi], bf[ni]);
        }

        if (i + 2 < nChunk) { issue(i + 2, (i + 2) % 3); CP_COMMIT(); }
    }

#pragma unroll
    for (int mi = 0; mi < 4; mi++) {
        int m0 = rowBase + wm + mi * 16 + grp;
        int m1 = m0 + 8;
#pragma unroll
        for (int ni = 0; ni < 8; ni++) {
            int n0 = colBase + wn + ni * 8 + thr * 2;
            if (m0 < M) {
                __half2 h = __floats2half2_rn(acc[mi][ni][0], acc[mi][ni][1]);
                *(__half2*)&C[(size_t)m0 * NH + n0] = h;
            }
            if (m1 < M) {
                __half2 h = __floats2half2_rn(acc[mi][ni][2], acc[mi][ni][3]);
                *(__half2*)&C[(size_t)m1 * NH + n0] = h;
            }
        }
    }
}

// ---------------- fused prep: halfx + packW1 + packW2 + zero -------------------
#define HX_BLOCKS  75000          // NNODE*NF/4 / 256 = 19.2M/256
#define PW1_BLOCKS 3072           // (NF/2)*NH / 256
#define PW2_BLOCKS 2048           // (NH/2)*NH / 256
#define Z_BLOCKS   256            // 65536/256 covers pooled & node arrays
#define PREP_BLOCKS (HX_BLOCKS + PW1_BLOCKS + PW2_BLOCKS + Z_BLOCKS)

__global__ __launch_bounds__(256)
void k_prep(const float* __restrict__ x, __half* __restrict__ xh,
            const float* __restrict__ W1, __half2* __restrict__ wp1,
            const float* __restrict__ W2, __half2* __restrict__ wp2,
            int* cnti, int* cur, float* pooled, float* cntg) {
    int b = blockIdx.x;
    if (b < HX_BLOCKS) {
        int i = b * 256 + threadIdx.x;                   // < 19.2M exactly
        float4 v = ((const float4*)x)[i];
        __half2 h0 = __floats2half2_rn(v.x, v.y);
        __half2 h1 = __floats2half2_rn(v.z, v.w);
        ((__half2*)xh)[2 * i]     = h0;
        ((__half2*)xh)[2 * i + 1] = h1;
    } else if (b < HX_BLOCKS + PW1_BLOCKS) {
        int i = (b - HX_BLOCKS) * 256 + threadIdx.x;     // < 786432 exactly
        int k2 = i >> 10, n = i & 1023;
        wp1[i] = __floats2half2_rn(W1[(size_t)(2 * k2) * NH + n],
                                   W1[(size_t)(2 * k2 + 1) * NH + n]);
    } else if (b < HX_BLOCKS + PW1_BLOCKS + PW2_BLOCKS) {
        int i = (b - HX_BLOCKS - PW1_BLOCKS) * 256 + threadIdx.x;  // < 524288
        int k2 = i >> 10, n = i & 1023;
        wp2[i] = __floats2half2_rn(W2[(size_t)(2 * k2) * NH + n],
                                   W2[(size_t)(2 * k2 + 1) * NH + n]);
    } else {
        int i = (b - HX_BLOCKS - PW1_BLOCKS - PW2_BLOCKS) * 256 + threadIdx.x;
        if (i < NG * NH) pooled[i] = 0.f;
        if (i < NNODE) { cnti[i] = 0; cur[i] = 0; }
        if (i < NG) cntg[i] = 0.f;
    }
}

// ---------------- CSR build ----------------------------------------------------
__global__ void k_count_i(const int* __restrict__ dst, int* cnti) {
    int e = blockIdx.x * blockDim.x + threadIdx.x;
    if (e < NEDGE) atomicAdd(&cnti[dst[e]], 1);
}

// fused: per-block exclusive scan + block totals + dis/selfw
__global__ __launch_bounds__(256)
void k_dis_scan1(const int* __restrict__ cnti, int* base, int* bsum,
                 float* dis, float* selfw) {
    __shared__ int s[256];
    int n = blockIdx.x * 256 + threadIdx.x;
    int v = (n < NNODE) ? cnti[n] : 0;
    if (n < NNODE) {
        float d = 1.0f + (float)v;
        dis[n]   = rsqrtf(d);
        selfw[n] = 1.0f / d;
    }
    s[threadIdx.x] = v;
    __syncthreads();
#pragma unroll
    for (int o = 1; o < 256; o <<= 1) {
        int t = (threadIdx.x >= o) ? s[threadIdx.x - o] : 0;
        __syncthreads();
        s[threadIdx.x] += t;
        __syncthreads();
    }
    if (n < NNODE) base[n] = s[threadIdx.x] - v;
    if (threadIdx.x == 255) bsum[blockIdx.x] = s[255];
}

__global__ __launch_bounds__(256)
void k_scan2(int* bsum) {
    __shared__ int s[256];
    int v = (threadIdx.x < NSCANB) ? bsum[threadIdx.x] : 0;
    s[threadIdx.x] = v;
    __syncthreads();
#pragma unroll
    for (int o = 1; o < 256; o <<= 1) {
        int t = (threadIdx.x >= o) ? s[threadIdx.x - o] : 0;
        __syncthreads();
        s[threadIdx.x] += t;
        __syncthreads();
    }
    if (threadIdx.x < NSCANB) bsum[threadIdx.x] = s[threadIdx.x] - v;
}

__global__ void k_scan3(int* base, const int* __restrict__ bsum) {
    int n = blockIdx.x * 256 + threadIdx.x;
    if (n < NNODE) base[n] += bsum[blockIdx.x];
    if (n == 0) base[NNODE] = NEDGE;
}

__global__ void k_fill(const int* __restrict__ src, const int* __restrict__ dst,
                       const float* __restrict__ dis, const int* __restrict__ base,
                       int* cur, int* csrs, float* csrw) {
    int e = blockIdx.x * blockDim.x + threadIdx.x;
    if (e < NEDGE) {
        int d = dst[e], s = src[e];
        int pos = base[d] + atomicAdd(&cur[d], 1);
        csrs[pos] = s;
        csrw[pos] = dis[s] * dis[d];
    }
}

// ---------------- fp16 gather (CSR), edge loop unrolled x4 ---------------------
__device__ __forceinline__ float4 ld_h4(const __half* row, int t) {
    uint2 q = ((const uint2*)row)[t];
    __half2 h0 = *reinterpret_cast<__half2*>(&q.x);
    __half2 h1 = *reinterpret_cast<__half2*>(&q.y);
    float2 f0 = __half22float2(h0);
    float2 f1 = __half22float2(h1);
    return make_float4(f0.x, f0.y, f1.x, f1.y);
}

__device__ __forceinline__ float4 gather_row(const __half* __restrict__ in,
                                             const int* __restrict__ csrs,
                                             const float* __restrict__ csrw,
                                             int n, int b0, int b1, float s, int t) {
    float4 v = ld_h4(in + (size_t)n * NH, t);
    float4 acc = make_float4(v.x * s, v.y * s, v.z * s, v.w * s);
    int j = b0;
    for (; j + 4 <= b1; j += 4) {
        int   s0 = csrs[j],     s1 = csrs[j + 1];
        int   s2 = csrs[j + 2], s3 = csrs[j + 3];
        float w0 = csrw[j],     w1 = csrw[j + 1];
        float w2 = csrw[j + 2], w3 = csrw[j + 3];
        float4 u0 = ld_h4(in + (size_t)s0 * NH, t);
        float4 u1 = ld_h4(in + (size_t)s1 * NH, t);
        float4 u2 = ld_h4(in + (size_t)s2 * NH, t);
        float4 u3 = ld_h4(in + (size_t)s3 * NH, t);
        acc.x += u0.x * w0 + u1.x * w1 + u2.x * w2 + u3.x * w3;
        acc.y += u0.y * w0 + u1.y * w1 + u2.y * w2 + u3.y * w3;
        acc.z += u0.z * w0 + u1.z * w1 + u2.z * w2 + u3.z * w3;
        acc.w += u0.w * w0 + u1.w * w1 + u2.w * w2 + u3.w * w3;
    }
    if (j + 2 <= b1) {
        int   s0 = csrs[j],   s1 = csrs[j + 1];
        float w0 = csrw[j],   w1 = csrw[j + 1];
        float4 u0 = ld_h4(in + (size_t)s0 * NH, t);
        float4 u1 = ld_h4(in + (size_t)s1 * NH, t);
        acc.x += u0.x * w0 + u1.x * w1;
        acc.y += u0.y * w0 + u1.y * w1;
        acc.z += u0.z * w0 + u1.z * w1;
        acc.w += u0.w * w0 + u1.w * w1;
        j += 2;
    }
    if (j < b1) {
        float4 u0 = ld_h4(in + (size_t)csrs[j] * NH, t);
        float w0 = csrw[j];
        acc.x += u0.x * w0; acc.y += u0.y * w0;
        acc.z += u0.z * w0; acc.w += u0.w * w0;
    }
    return acc;
}

__global__ __launch_bounds__(256)
void k_gather_relu_h(const __half* __restrict__ in, __half* __restrict__ out,
                     const int* __restrict__ csrs, const float* __restrict__ csrw,
                     const int* __restrict__ base, const float* __restrict__ selfw,
                     const float* __restrict__ bias) {
    int n = blockIdx.x;
    int t = threadIdx.x;
    float4 acc = gather_row(in, csrs, csrw, n, base[n], base[n + 1], selfw[n], t);
    int h = t * 4;
    acc.x = fmaxf(acc.x + bias[h + 0], 0.f);
    acc.y = fmaxf(acc.y + bias[h + 1], 0.f);
    acc.z = fmaxf(acc.z + bias[h + 2], 0.f);
    acc.w = fmaxf(acc.w + bias[h + 3], 0.f);
    __half2 o0 = __floats2half2_rn(acc.x, acc.y);
    __half2 o1 = __floats2half2_rn(acc.z, acc.w);
    uint2 q;
    q.x = *reinterpret_cast<uint32_t*>(&o0);
    q.y = *reinterpret_cast<uint32_t*>(&o1);
    ((uint2*)(out + (size_t)n * NH))[t] = q;
}

__global__ __launch_bounds__(256)
void k_gather_pool_h(const __half* __restrict__ in, const int* __restrict__ batch,
                     const int* __restrict__ csrs, const float* __restrict__ csrw,
                     const int* __restrict__ base, const float* __restrict__ selfw,
                     const float* __restrict__ bias, float* __restrict__ pooled,
                     float* __restrict__ cntg) {
    int n = blockIdx.x;
    int t = threadIdx.x;
    float4 acc = gather_row(in, csrs, csrw, n, base[n], base[n + 1], selfw[n], t);
    int h = t * 4;
    acc.x = fmaxf(acc.x + bias[h + 0], 0.f);
    acc.y = fmaxf(acc.y + bias[h + 1], 0.f);
    acc.z = fmaxf(acc.z + bias[h + 2], 0.f);
    acc.w = fmaxf(acc.w + bias[h + 3], 0.f);
    int g = batch[n];
    red_add_v4(pooled + (size_t)g * NH + h, acc);
    if (t == 0) atomicAdd(&cntg[g], 1.0f);
}

// ---------------- head (comb fused into mlp1) ----------------------------------
__global__ __launch_bounds__(256)
void k_mlp1(const float* __restrict__ gx, const float* __restrict__ pooled,
            const float* __restrict__ cntg, const float* __restrict__ fw1,
            const float* __restrict__ fb1, float* __restrict__ hid) {
    __shared__ float sc[32][65];
    __shared__ float rc[64];
    if (threadIdx.x < 64) rc[threadIdx.x] = 1.0f / fmaxf(cntg[threadIdx.x], 1.0f);
    __syncthreads();

    int j  = blockIdx.x * 16 + (threadIdx.x & 15);
    int gq = threadIdx.x >> 4;
    float acc[4] = {0.f, 0.f, 0.f, 0.f};
    for (int kb = 0; kb < NCOMB; kb += 32) {
#pragma unroll
        for (int u = 0; u < 8; u++) {
            int l = threadIdx.x + 256 * u;
            int g = l >> 5, kk = l & 31;
            int i = kb + kk;
            float v;
            if (i < NF) v = gx[(size_t)g * NF + i];
            else        v = pooled[(size_t)g * NH + (i - NF)] * rc[g];
            sc[kk][g] = v;
        }
        __syncthreads();
#pragma unroll 8
        for (int kk = 0; kk < 32; kk++) {
            float w = fw1[(size_t)(kb + kk) * NFUSE + j];
#pragma unroll
            for (int q = 0; q < 4; q++) acc[q] += sc[kk][gq * 4 + q] * w;
        }
        __syncthreads();
    }
#pragma unroll
    for (int q = 0; q < 4; q++) {
        int g = gq * 4 + q;
        hid[(size_t)g * NFUSE + j] = fmaxf(acc[q] + fb1[j], 0.f);
    }
}

__global__ __launch_bounds__(128)
void k_mlp2(const float* __restrict__ hid, const float* __restrict__ fw2,
            const float* __restrict__ fb2, float* __restrict__ out) {
    __shared__ float sh[NFUSE];
    int g = blockIdx.x;
    for (int i = threadIdx.x; i < NFUSE; i += blockDim.x)
        sh[i] = hid[(size_t)g * NFUSE + i];
    __syncthreads();
    int c = threadIdx.x;
    if (c < NC) {
        float acc = 0.f;
#pragma unroll 4
        for (int k = 0; k < NFUSE; k++) acc += sh[k] * fw2[(size_t)k * NC + c];
        out[(size_t)g * NC + c] = acc + fb2[c];
    }
}

// ---------------- launch --------------------------------------------------------
extern "C" void kernel_launch(void* const* d_in, const int* in_sizes, int n_in,
                              void* d_out, int out_size) {
    const float* gx    = (const float*)d_in[0];
    const float* x     = (const float*)d_in[1];
    const int*   eidx  = (const int*)  d_in[2];
    const int*   batch = (const int*)  d_in[3];
    const float* W1    = (const float*)d_in[4];
    const float* b1    = (const float*)d_in[5];
    const float* W2    = (const float*)d_in[6];
    const float* b2    = (const float*)d_in[7];
    const float* fw1   = (const float*)d_in[8];
    const float* fb1   = (const float*)d_in[9];
    const float* fw2   = (const float*)d_in[10];
    const float* fb2   = (const float*)d_in[11];
    float* out = (float*)d_out;

    const int* src = eidx;
    const int* dst = eidx + NEDGE;

    __half *xh, *b1h, *b2h;
    __half2 *wp1, *wp2;
    float *dis, *selfw, *csrw, *pooled, *cntg, *hid;
    int *cnti, *cur, *basev, *bsum, *csrs;
    cudaGetSymbolAddress((void**)&xh,     g_xh);
    cudaGetSymbolAddress((void**)&b1h,    g_b1h);
    cudaGetSymbolAddress((void**)&b2h,    g_b2h);
    cudaGetSymbolAddress((void**)&wp1,    g_wp1);
    cudaGetSymbolAddress((void**)&wp2,    g_wp2);
    cudaGetSymbolAddress((void**)&dis,    g_dis);
    cudaGetSymbolAddress((void**)&selfw,  g_selfw);
    cudaGetSymbolAddress((void**)&cnti,   g_cnti);
    cudaGetSymbolAddress((void**)&cur,    g_cur);
    cudaGetSymbolAddress((void**)&basev,  g_basev);
    cudaGetSymbolAddress((void**)&bsum,   g_bsum);
    cudaGetSymbolAddress((void**)&csrs,   g_csrs);
    cudaGetSymbolAddress((void**)&csrw,   g_csrw);
    cudaGetSymbolAddress((void**)&pooled, g_pooled);
    cudaGetSymbolAddress((void**)&cntg,   g_cntg);
    cudaGetSymbolAddress((void**)&hid,    g_hid);

    cudaFuncSetAttribute(gemm_h, cudaFuncAttributeMaxDynamicSharedMemorySize,
                         GEMM_SMEM);

    const int TPB = 256;
    const int edgeBlocks = (NEDGE + TPB - 1) / TPB;

    dim3 gg(NH / 128, (NNODE + 127) / 128);   // (8, 391)

    // 12 launches (was 17); gemm1 at slot 4 (ncu capture window)
    k_prep      <<<PREP_BLOCKS, TPB>>>(x, xh, W1, wp1, W2, wp2,
                                       cnti, cur, pooled, cntg);              // 1
    k_count_i   <<<edgeBlocks, TPB>>>(dst, cnti);                             // 2
    k_dis_scan1 <<<NSCANB, TPB>>>(cnti, basev, bsum, dis, selfw);             // 3
    gemm_h      <<<gg, 128, GEMM_SMEM>>>(xh, wp1, b1h, NNODE, NF, NF / 64);   // 4
    k_scan2     <<<1, TPB>>>(bsum);                                           // 5
    k_scan3     <<<NSCANB, TPB>>>(basev, bsum);                               // 6
    k_fill      <<<edgeBlocks, TPB>>>(src, dst, dis, basev, cur, csrs, csrw); // 7
    k_gather_relu_h<<<NNODE, 256>>>(b1h, b2h, csrs, csrw, basev, selfw, b1);  // 8
    gemm_h      <<<gg, 128, GEMM_SMEM>>>(b2h, wp2, b1h, NNODE, NH, NH / 64);  // 9
    k_gather_pool_h<<<NNODE, 256>>>(b1h, batch, csrs, csrw, basev, selfw, b2,
                                    pooled, cntg);                            // 10
    k_mlp1      <<<NFUSE / 16, 256>>>(gx, pooled, cntg, fw1, fb1, hid);       // 11
    k_mlp2      <<<NG, 128>>>(hid, fw2, fb2, out);                            // 12
}

// round 16
// speedup vs baseline: 1.0593x; 1.0593x over previous
#include <cuda_runtime.h>
#include <cuda_fp16.h>
#include <cstdint>

#define NNODE 50000
#define NEDGE 200000
#define NG    64
#define NF    1536
#define NH    1024
#define NC    80
#define NFUSE 1024
#define NCOMB (NF + NH)   // 2560
#define NSCANB 196        // ceil(NNODE/256)

// ---------------- scratch (device globals) ----------------------------------
__device__ __half  g_xh  [(size_t)NNODE * NF];      // x in fp16
__device__ __half  g_b1h [(size_t)NNODE * NH];      // gemm out / reuse
__device__ __half  g_b2h [(size_t)NNODE * NH];      // gather out
__device__ __half2 g_wp1 [(size_t)(NF / 2) * NH];   // W1 k-pair packed
__device__ __half2 g_wp2 [(size_t)(NH / 2) * NH];   // W2 k-pair packed
__device__ float g_dis  [NNODE];
__device__ float g_selfw[NNODE];
__device__ int   g_cnti [NNODE];
__device__ int   g_cur  [NNODE];
__device__ int   g_basev[NNODE + 1];
__device__ int   g_bsum [256];
__device__ int   g_csrs [NEDGE];
__device__ float g_csrw [NEDGE];
__device__ float g_pooled[NG * NH];
__device__ float g_cntg [NG];
__device__ float g_comb[NG * NCOMB];
__device__ float g_hid [NG * NFUSE];

// ---------------- helpers ----------------------------------------------------
__device__ __forceinline__ void mma_f16(float c[4], const uint32_t a[4],
                                        const uint32_t b[2]) {
    asm volatile(
        "mma.sync.aligned.m16n8k16.row.col.f32.f16.f16.f32 "
        "{%0,%1,%2,%3}, {%4,%5,%6,%7}, {%8,%9}, {%0,%1,%2,%3};"
        : "+f"(c[0]), "+f"(c[1]), "+f"(c[2]), "+f"(c[3])
        : "r"(a[0]), "r"(a[1]), "r"(a[2]), "r"(a[3]), "r"(b[0]), "r"(b[1]));
}

__device__ __forceinline__ void red_add_v4(float* p, float4 v) {
    asm volatile("red.add.v4.f32 [%0], {%1,%2,%3,%4};"
                 :: "l"(p), "f"(v.x), "f"(v.y), "f"(v.z), "f"(v.w) : "memory");
}

#define CP_ASYNC16(dst, src, sz) \
    asm volatile("cp.async.cg.shared.global [%0], [%1], 16, %2;" \
                 :: "r"(dst), "l"(src), "r"(sz) : "memory")
#define CP_COMMIT()  asm volatile("cp.async.commit_group;" ::: "memory")
#define CP_WAIT(n)   asm volatile("cp.async.wait_group %0;" :: "n"(n) : "memory")

// ---------------- fp16 mma.sync GEMM, BK=64, early-issue ----------------------
// C[M,1024](fp16) = A[M,K](fp16) @ W[K,1024].  CTA tile 128x128, BK=64,
// 4 warps (2m x 2n, warp tile 64x64 = 4x8 m16n8k16 frags), 3-stage cp.async,
// 2 CTAs/SM.  Loads for chunk i+2 issued BEFORE compute of chunk i (stage
// (i+2)%3's last readers completed before this iter's __syncthreads).
#define A_STRIDE 36              // u32 per A row (32 data + 4 pad)
#define B_STRIDE 136             // u32 per B k2-row
#define A_U32    (128 * A_STRIDE)          // 4608
#define B_U32    (32 * B_STRIDE)           // 4352
#define STAGE_U32 (A_U32 + B_U32)          // 8960
#define GEMM_SMEM (3 * STAGE_U32 * 4)      // 107520 B

__global__ __launch_bounds__(128, 2)
void gemm_h(const __half* __restrict__ A, const __half2* __restrict__ Wp,
            __half* __restrict__ C, int M, int K, int nChunk) {
    extern __shared__ uint32_t sm[];
    uint32_t smb;
    asm("{ .reg .u64 t; cvta.to.shared.u64 t, %1; cvt.u32.u64 %0, t; }"
        : "=r"(smb) : "l"(sm));

    const int tid  = threadIdx.x;
    const int lane = tid & 31;
    const int warp = tid >> 5;
    const int wm   = (warp & 1) * 64;
    const int wn   = (warp >> 1) * 64;
    const int grp  = lane >> 2;
    const int thr  = lane & 3;

    const int rowBase = blockIdx.y * 128;
    const int colBase = blockIdx.x * 128;

    auto issue = [&](int chunk, int st) {
        const uint32_t base = smb + (uint32_t)st * (STAGE_U32 * 4);
        const int k0  = chunk * 64;       // halves
        const int k02 = chunk * 32;       // half2 rows of Wp
#pragma unroll
        for (int u = 0; u < 8; u++) {     // A: 1024 16B chunks / 128 thr
            int t = tid + u * 128;
            int r = t >> 3, c = t & 7;
            uint32_t dst = base + (uint32_t)(r * A_STRIDE + c * 4) * 4u;
            int row = rowBase + r;
            int ok  = row < M;
            const __half* srcp = A + (size_t)(ok ? row : 0) * K + k0 + c * 8;
            CP_ASYNC16(dst, srcp, ok ? 16 : 0);
        }
#pragma unroll
        for (int u = 0; u < 8; u++) {     // B: 1024 16B chunks / 128 thr
            int t = tid + u * 128;
            int k2 = t >> 5, c = t & 31;
            uint32_t dst = base + (uint32_t)(A_U32 + k2 * B_STRIDE + c * 4) * 4u;
            const __half2* srcp = Wp + (size_t)(k02 + k2) * NH + colBase + c * 4;
            CP_ASYNC16(dst, srcp, 16);
        }
    };

    float acc[4][8][4];
#pragma unroll
    for (int i = 0; i < 4; i++)
#pragma unroll
        for (int j = 0; j < 8; j++)
#pragma unroll
            for (int r = 0; r < 4; r++) acc[i][j][r] = 0.f;

    issue(0, 0); CP_COMMIT();
    issue(1, 1); CP_COMMIT();

    for (int i = 0; i < nChunk; i++) {
        const int si = i % 3;
        CP_WAIT(1);                 // chunk i resident (i+1 may be pending)
        __syncthreads();            // all warps done reading stage (i+2)%3

        // early issue: overlap chunk i+2's loads with chunk i's compute
        if (i + 2 < nChunk) { issue(i + 2, (i + 2) % 3); CP_COMMIT(); }

        const uint32_t* As = sm + si * STAGE_U32;
        const uint32_t* Bs = sm + si * STAGE_U32 + A_U32;

#pragma unroll
        for (int kk = 0; kk < 4; kk++) {       // four k16 groups per chunk
            const int kb2 = kk * 8;            // u32 (half2) offset
            uint32_t af[4][4], bf[8][2];
#pragma unroll
            for (int mi = 0; mi < 4; mi++) {
                int m = wm + mi * 16 + grp;
                af[mi][0] = As[m * A_STRIDE + kb2 + thr];
                af[mi][1] = As[(m + 8) * A_STRIDE + kb2 + thr];
                af[mi][2] = As[m * A_STRIDE + kb2 + 4 + thr];
                af[mi][3] = As[(m + 8) * A_STRIDE + kb2 + 4 + thr];
            }
#pragma unroll
            for (int ni = 0; ni < 8; ni++) {
                int n = wn + ni * 8 + grp;
                bf[ni][0] = Bs[(kb2 + thr) * B_STRIDE + n];
                bf[ni][1] = Bs[(kb2 + 4 + thr) * B_STRIDE + n];
            }
#pragma unroll
            for (int mi = 0; mi < 4; mi++)
#pragma unroll
                for (int ni = 0; ni < 8; ni++)
                    mma_f16(acc[mi][ni], af[mi], bf[ni]);
        }
    }

    // epilogue: fp32 acc -> fp16 store
#pragma unroll
    for (int mi = 0; mi < 4; mi++) {
        int m0 = rowBase + wm + mi * 16 + grp;
        int m1 = m0 + 8;
#pragma unroll
        for (int ni = 0; ni < 8; ni++) {
            int n0 = colBase + wn + ni * 8 + thr * 2;
            if (m0 < M) {
                __half2 h = __floats2half2_rn(acc[mi][ni][0], acc[mi][ni][1]);
                *(__half2*)&C[(size_t)m0 * NH + n0] = h;
            }
            if (m1 < M) {
                __half2 h = __floats2half2_rn(acc[mi][ni][2], acc[mi][ni][3]);
                *(__half2*)&C[(size_t)m1 * NH + n0] = h;
            }
        }
    }
}

// ---------------- conversions ---------------------------------------------------
__global__ void k_halfx(const float* __restrict__ x, __half* __restrict__ xh,
                        int total4) {
    int i = blockIdx.x * blockDim.x + threadIdx.x;
    if (i < total4) {
        float4 v = ((const float4*)x)[i];
        __half2 h0 = __floats2half2_rn(v.x, v.y);
        __half2 h1 = __floats2half2_rn(v.z, v.w);
        ((__half2*)xh)[2 * i]     = h0;
        ((__half2*)xh)[2 * i + 1] = h1;
    }
}

__global__ void k_packW(const float* __restrict__ W, __half2* __restrict__ Wp,
                        int k2total) {
    int i = blockIdx.x * blockDim.x + threadIdx.x;
    if (i < k2total * NH) {
        int k2 = i >> 10, n = i & 1023;
        float a = W[(size_t)(2 * k2) * NH + n];
        float b = W[(size_t)(2 * k2 + 1) * NH + n];
        Wp[i] = __floats2half2_rn(a, b);
    }
}

// ---------------- CSR build ----------------------------------------------------
__global__ void k_zero_all(int* cnti, int* cur, float* pooled, float* cntg) {
    int i = blockIdx.x * blockDim.x + threadIdx.x;
    if (i < NNODE) { cnti[i] = 0; cur[i] = 0; }
    if (i < NG * NH) pooled[i] = 0.f;
    if (i < NG) cntg[i] = 0.f;
}

__global__ void k_count_i(const int* __restrict__ dst, int* cnti) {
    int e = blockIdx.x * blockDim.x + threadIdx.x;
    if (e < NEDGE) atomicAdd(&cnti[dst[e]], 1);
}

__global__ void k_dis(const int* __restrict__ cnti, float* dis, float* selfw) {
    int n = blockIdx.x * blockDim.x + threadIdx.x;
    if (n < NNODE) {
        float d = 1.0f + (float)cnti[n];
        dis[n]   = rsqrtf(d);
        selfw[n] = 1.0f / d;
    }
}

__global__ __launch_bounds__(256)
void k_scan1(const int* __restrict__ cnti, int* base, int* bsum) {
    __shared__ int s[256];
    int n = blockIdx.x * 256 + threadIdx.x;
    int v = (n < NNODE) ? cnti[n] : 0;
    s[threadIdx.x] = v;
    __syncthreads();
#pragma unroll
    for (int o = 1; o < 256; o <<= 1) {
        int t = (threadIdx.x >= o) ? s[threadIdx.x - o] : 0;
        __syncthreads();
        s[threadIdx.x] += t;
        __syncthreads();
    }
    if (n < NNODE) base[n] = s[threadIdx.x] - v;
    if (threadIdx.x == 255) bsum[blockIdx.x] = s[255];
}

__global__ __launch_bounds__(256)
void k_scan2(int* bsum) {
    __shared__ int s[256];
    int v = (threadIdx.x < NSCANB) ? bsum[threadIdx.x] : 0;
    s[threadIdx.x] = v;
    __syncthreads();
#pragma unroll
    for (int o = 1; o < 256; o <<= 1) {
        int t = (threadIdx.x >= o) ? s[threadIdx.x - o] : 0;
        __syncthreads();
        s[threadIdx.x] += t;
        __syncthreads();
    }
    if (threadIdx.x < NSCANB) bsum[threadIdx.x] = s[threadIdx.x] - v;
}

__global__ void k_scan3(int* base, const int* __restrict__ bsum) {
    int n = blockIdx.x * 256 + threadIdx.x;
    if (n < NNODE) base[n] += bsum[blockIdx.x];
    if (n == 0) base[NNODE] = NEDGE;
}

__global__ void k_fill(const int* __restrict__ src, const int* __restrict__ dst,
                       const float* __restrict__ dis, const int* __restrict__ base,
                       int* cur, int* csrs, float* csrw) {
    int e = blockIdx.x * blockDim.x + threadIdx.x;
    if (e < NEDGE) {
        int d = dst[e], s = src[e];
        int pos = base[d] + atomicAdd(&cur[d], 1);
        csrs[pos] = s;
        csrw[pos] = dis[s] * dis[d];
    }
}

// ---------------- fp16 gather (CSR), edge loop unrolled x4 ---------------------
__device__ __forceinline__ float4 ld_h4(const __half* row, int t) {
    uint2 q = ((const uint2*)row)[t];
    __half2 h0 = *reinterpret_cast<__half2*>(&q.x);
    __half2 h1 = *reinterpret_cast<__half2*>(&q.y);
    float2 f0 = __half22float2(h0);
    float2 f1 = __half22float2(h1);
    return make_float4(f0.x, f0.y, f1.x, f1.y);
}

__device__ __forceinline__ float4 gather_row(const __half* __restrict__ in,
                                             const int* __restrict__ csrs,
                                             const float* __restrict__ csrw,
                                             int n, int b0, int b1, float s, int t) {
    float4 v = ld_h4(in + (size_t)n * NH, t);
    float4 acc = make_float4(v.x * s, v.y * s, v.z * s, v.w * s);
    int j = b0;
    for (; j + 4 <= b1; j += 4) {
        int   s0 = csrs[j],     s1 = csrs[j + 1];
        int   s2 = csrs[j + 2], s3 = csrs[j + 3];
        float w0 = csrw[j],     w1 = csrw[j + 1];
        float w2 = csrw[j + 2], w3 = csrw[j + 3];
        float4 u0 = ld_h4(in + (size_t)s0 * NH, t);
        float4 u1 = ld_h4(in + (size_t)s1 * NH, t);
        float4 u2 = ld_h4(in + (size_t)s2 * NH, t);
        float4 u3 = ld_h4(in + (size_t)s3 * NH, t);
        acc.x += u0.x * w0 + u1.x * w1 + u2.x * w2 + u3.x * w3;
        acc.y += u0.y * w0 + u1.y * w1 + u2.y * w2 + u3.y * w3;
        acc.z += u0.z * w0 + u1.z * w1 + u2.z * w2 + u3.z * w3;
        acc.w += u0.w * w0 + u1.w * w1 + u2.w * w2 + u3.w * w3;
    }
    if (j + 2 <= b1) {
        int   s0 = csrs[j],   s1 = csrs[j + 1];
        float w0 = csrw[j],   w1 = csrw[j + 1];
        float4 u0 = ld_h4(in + (size_t)s0 * NH, t);
        float4 u1 = ld_h4(in + (size_t)s1 * NH, t);
        acc.x += u0.x * w0 + u1.x * w1;
        acc.y += u0.y * w0 + u1.y * w1;
        acc.z += u0.z * w0 + u1.z * w1;
        acc.w += u0.w * w0 + u1.w * w1;
        j += 2;
    }
    if (j < b1) {
        float4 u0 = ld_h4(in + (size_t)csrs[j] * NH, t);
        float w0 = csrw[j];
        acc.x += u0.x * w0; acc.y += u0.y * w0;
        acc.z += u0.z * w0; acc.w += u0.w * w0;
    }
    return acc;
}

__global__ __launch_bounds__(256)
void k_gather_relu_h(const __half* __restrict__ in, __half* __restrict__ out,
                     const int* __restrict__ csrs, const float* __restrict__ csrw,
                     const int* __restrict__ base, const float* __restrict__ selfw,
                     const float* __restrict__ bias) {
    int n = blockIdx.x;
    int t = threadIdx.x;
    float4 acc = gather_row(in, csrs, csrw, n, base[n], base[n + 1], selfw[n], t);
    int h = t * 4;
    acc.x = fmaxf(acc.x + bias[h + 0], 0.f);
    acc.y = fmaxf(acc.y + bias[h + 1], 0.f);
    acc.z = fmaxf(acc.z + bias[h + 2], 0.f);
    acc.w = fmaxf(acc.w + bias[h + 3], 0.f);
    __half2 o0 = __floats2half2_rn(acc.x, acc.y);
    __half2 o1 = __floats2half2_rn(acc.z, acc.w);
    uint2 q;
    q.x = *reinterpret_cast<uint32_t*>(&o0);
    q.y = *reinterpret_cast<uint32_t*>(&o1);
    ((uint2*)(out + (size_t)n * NH))[t] = q;
}

__global__ __launch_bounds__(256)
void k_gather_pool_h(const __half* __restrict__ in, const int* __restrict__ batch,
                     const int* __restrict__ csrs, const float* __restrict__ csrw,
                     const int* __restrict__ base, const float* __restrict__ selfw,
                     const float* __restrict__ bias, float* __restrict__ pooled,
                     float* __restrict__ cntg) {
    int n = blockIdx.x;
    int t = threadIdx.x;
    float4 acc = gather_row(in, csrs, csrw, n, base[n], base[n + 1], selfw[n], t);
    int h = t * 4;
    acc.x = fmaxf(acc.x + bias[h + 0], 0.f);
    acc.y = fmaxf(acc.y + bias[h + 1], 0.f);
    acc.z = fmaxf(acc.z + bias[h + 2], 0.f);
    acc.w = fmaxf(acc.w + bias[h + 3], 0.f);
    int g = batch[n];
    red_add_v4(pooled + (size_t)g * NH + h, acc);
    if (t == 0) atomicAdd(&cntg[g], 1.0f);
}

// ---------------- head ---------------------------------------------------------
__global__ void k_comb(const float* __restrict__ gx, const float* __restrict__ pooled,
                       const float* __restrict__ cntg, float* __restrict__ comb) {
    int g = blockIdx.y;
    int i = blockIdx.x * blockDim.x + threadIdx.x;
    float v;
    if (i < NF) v = gx[(size_t)g * NF + i];
    else        v = pooled[(size_t)g * NH + (i - NF)] / fmaxf(cntg[g], 1.0f);
    comb[(size_t)g * NCOMB + i] = v;
}

__global__ __launch_bounds__(256)
void k_mlp1(const float* __restrict__ comb, const float* __restrict__ fw1,
            const float* __restrict__ fb1, float* __restrict__ hid) {
    __shared__ float sc[32][65];
    int j  = blockIdx.x * 16 + (threadIdx.x & 15);
    int gq = threadIdx.x >> 4;
    float acc[4] = {0.f, 0.f, 0.f, 0.f};
    for (int kb = 0; kb < NCOMB; kb += 32) {
#pragma unroll
        for (int u = 0; u < 8; u++) {
            int l = threadIdx.x + 256 * u;
            int g = l >> 5, kk = l & 31;
            sc[kk][g] = comb[(size_t)g * NCOMB + kb + kk];
        }
        __syncthreads();
#pragma unroll 8
        for (int kk = 0; kk < 32; kk++) {
            float w = fw1[(size_t)(kb + kk) * NFUSE + j];
#pragma unroll
            for (int q = 0; q < 4; q++) acc[q] += sc[kk][gq * 4 + q] * w;
        }
        __syncthreads();
    }
#pragma unroll
    for (int q = 0; q < 4; q++) {
        int g = gq * 4 + q;
        hid[(size_t)g * NFUSE + j] = fmaxf(acc[q] + fb1[j], 0.f);
    }
}

__global__ __launch_bounds__(128)
void k_mlp2(const float* __restrict__ hid, const float* __restrict__ fw2,
            const float* __restrict__ fb2, float* __restrict__ out) {
    __shared__ float sh[NFUSE];
    int g = blockIdx.x;
    for (int i = threadIdx.x; i < NFUSE; i += blockDim.x)
        sh[i] = hid[(size_t)g * NFUSE + i];
    __syncthreads();
    int c = threadIdx.x;
    if (c < NC) {
        float acc = 0.f;
#pragma unroll 4
        for (int k = 0; k < NFUSE; k++) acc += sh[k] * fw2[(size_t)k * NC + c];
        out[(size_t)g * NC + c] = acc + fb2[c];
    }
}

// ---------------- launch --------------------------------------------------------
extern "C" void kernel_launch(void* const* d_in, const int* in_sizes, int n_in,
                              void* d_out, int out_size) {
    const float* gx    = (const float*)d_in[0];
    const float* x     = (const float*)d_in[1];
    const int*   eidx  = (const int*)  d_in[2];
    const int*   batch = (const int*)  d_in[3];
    const float* W1    = (const float*)d_in[4];
    const float* b1    = (const float*)d_in[5];
    const float* W2    = (const float*)d_in[6];
    const float* b2    = (const float*)d_in[7];
    const float* fw1   = (const float*)d_in[8];
    const float* fb1   = (const float*)d_in[9];
    const float* fw2   = (const float*)d_in[10];
    const float* fb2   = (const float*)d_in[11];
    float* out = (float*)d_out;

    const int* src = eidx;
    const int* dst = eidx + NEDGE;

    __half *xh, *b1h, *b2h;
    __half2 *wp1, *wp2;
    float *dis, *selfw, *csrw, *pooled, *cntg, *comb, *hid;
    int *cnti, *cur, *basev, *bsum, *csrs;
    cudaGetSymbolAddress((void**)&xh,     g_xh);
    cudaGetSymbolAddress((void**)&b1h,    g_b1h);
    cudaGetSymbolAddress((void**)&b2h,    g_b2h);
    cudaGetSymbolAddress((void**)&wp1,    g_wp1);
    cudaGetSymbolAddress((void**)&wp2,    g_wp2);
    cudaGetSymbolAddress((void**)&dis,    g_dis);
    cudaGetSymbolAddress((void**)&selfw,  g_selfw);
    cudaGetSymbolAddress((void**)&cnti,   g_cnti);
    cudaGetSymbolAddress((void**)&cur,    g_cur);
    cudaGetSymbolAddress((void**)&basev,  g_basev);
    cudaGetSymbolAddress((void**)&bsum,   g_bsum);
    cudaGetSymbolAddress((void**)&csrs,   g_csrs);
    cudaGetSymbolAddress((void**)&csrw,   g_csrw);
    cudaGetSymbolAddress((void**)&pooled, g_pooled);
    cudaGetSymbolAddress((void**)&cntg,   g_cntg);
    cudaGetSymbolAddress((void**)&comb,   g_comb);
    cudaGetSymbolAddress((void**)&hid,    g_hid);

    cudaFuncSetAttribute(gemm_h, cudaFuncAttributeMaxDynamicSharedMemorySize,
                         GEMM_SMEM);

    const int TPB = 256;
    const int edgeBlocks = (NEDGE + TPB - 1) / TPB;
    const int zb = ((NNODE > NG * NH ? NNODE : NG * NH) + TPB - 1) / TPB;

    dim3 gg(NH / 128, (NNODE + 127) / 128);   // (8, 391)

    // R14 launch structure; gemm1 at slot 4 (ncu capture window)
    k_halfx <<<(NNODE * NF / 4 + TPB - 1) / TPB, TPB>>>(x, xh, NNODE * NF / 4); // 1
    k_packW <<<((NF / 2) * NH + TPB - 1) / TPB, TPB>>>(W1, wp1, NF / 2);        // 2
    k_zero_all<<<zb, TPB>>>(cnti, cur, pooled, cntg);                           // 3
    gemm_h  <<<gg, 128, GEMM_SMEM>>>(xh, wp1, b1h, NNODE, NF, NF / 64);         // 4
    k_count_i<<<edgeBlocks, TPB>>>(dst, cnti);                                  // 5
    k_dis   <<<NSCANB, TPB>>>(cnti, dis, selfw);                                // 6
    k_scan1 <<<NSCANB, TPB>>>(cnti, basev, bsum);                               // 7
    k_scan2 <<<1, TPB>>>(bsum);                                                 // 8
    k_scan3 <<<NSCANB, TPB>>>(basev, bsum);                                     // 9
    k_fill  <<<edgeBlocks, TPB>>>(src, dst, dis, basev, cur, csrs, csrw);       // 10
    k_gather_relu_h<<<NNODE, 256>>>(b1h, b2h, csrs, csrw, basev, selfw, b1);    // 11

    k_packW <<<((NH / 2) * NH + TPB - 1) / TPB, TPB>>>(W2, wp2, NH / 2);        // 12
    gemm_h  <<<gg, 128, GEMM_SMEM>>>(b2h, wp2, b1h, NNODE, NH, NH / 64);        // 13
    k_gather_pool_h<<<NNODE, 256>>>(b1h, batch, csrs, csrw, basev, selfw, b2,
                                    pooled, cntg);                              // 14

    dim3 gc(NCOMB / TPB, NG);
    k_comb<<<gc, TPB>>>(gx, pooled, cntg, comb);                                // 15
    k_mlp1<<<NFUSE / 16, 256>>>(comb, fw1, fb1, hid);                           // 16
    k_mlp2<<<NG, 128>>>(hid, fw2, fb2, out);                                    // 17
}

// round 17
// speedup vs baseline: 1.1020x; 1.0403x over previous
#include <cuda_runtime.h>
#include <cuda_fp16.h>
#include <cstdint>

#define NNODE 50000
#define NEDGE 200000
#define NG    64
#define NF    1536
#define NH    1024
#define NC    80
#define NFUSE 1024
#define NCOMB (NF + NH)   // 2560
#define NSCANB 196        // ceil(NNODE/256)

// ---------------- scratch (device globals) ----------------------------------
__device__ __half  g_xh  [(size_t)NNODE * NF];      // x in fp16
__device__ __half  g_b1h [(size_t)NNODE * NH];      // gemm out / reuse
__device__ __half  g_b2h [(size_t)NNODE * NH];      // gather out
__device__ __half2 g_wp1 [(size_t)(NF / 2) * NH];   // W1 k-pair packed
__device__ __half2 g_wp2 [(size_t)(NH / 2) * NH];   // W2 k-pair packed
__device__ float g_dis  [NNODE];
__device__ float g_selfw[NNODE];
__device__ int   g_cnti [NNODE];
__device__ int   g_cur  [NNODE];
__device__ int   g_basev[NNODE + 1];
__device__ int   g_bsum [256];
__device__ int   g_csrs [NEDGE];
__device__ float g_csrw [NEDGE];
__device__ float g_pooled[NG * NH];
__device__ float g_cntg [NG];
__device__ float g_comb[NG * NCOMB];
__device__ float g_hid [NG * NFUSE];

// ---------------- helpers ----------------------------------------------------
__device__ __forceinline__ void mma_f16(float c[4], const uint32_t a[4],
                                        const uint32_t b[2]) {
    asm volatile(
        "mma.sync.aligned.m16n8k16.row.col.f32.f16.f16.f32 "
        "{%0,%1,%2,%3}, {%4,%5,%6,%7}, {%8,%9}, {%0,%1,%2,%3};"
        : "+f"(c[0]), "+f"(c[1]), "+f"(c[2]), "+f"(c[3])
        : "r"(a[0]), "r"(a[1]), "r"(a[2]), "r"(a[3]), "r"(b[0]), "r"(b[1]));
}

#define LDSM_X4(r0, r1, r2, r3, addr) \
    asm volatile("ldmatrix.sync.aligned.m8n8.x4.shared.b16 {%0,%1,%2,%3}, [%4];" \
                 : "=r"(r0), "=r"(r1), "=r"(r2), "=r"(r3) : "r"(addr))

__device__ __forceinline__ void red_add_v4(float* p, float4 v) {
    asm volatile("red.add.v4.f32 [%0], {%1,%2,%3,%4};"
                 :: "l"(p), "f"(v.x), "f"(v.y), "f"(v.z), "f"(v.w) : "memory");
}

#define CP_ASYNC16(dst, src, sz) \
    asm volatile("cp.async.cg.shared.global [%0], [%1], 16, %2;" \
                 :: "r"(dst), "l"(src), "r"(sz) : "memory")
#define CP_COMMIT()  asm volatile("cp.async.commit_group;" ::: "memory")
#define CP_WAIT(n)   asm volatile("cp.async.wait_group %0;" :: "n"(n) : "memory")

// ---------------- fp16 mma.sync GEMM, BK=64, ldmatrix A -----------------------
// C[M,1024](fp16) = A[M,K](fp16) @ W[K,1024].  CTA tile 128x128, BK=64,
// 4 warps (2m x 2n, warp tile 64x64 = 4x8 m16n8k16 frags), 3-stage cp.async,
// 2 CTAs/SM, late issue (R14 ordering).  A fragments via ldmatrix.x4
// (canonical m8n8.b16 mapping; stride 36 u32 -> 8 rows hit banks 0,4..28).
#define A_STRIDE 36              // u32 per A row (32 data + 4 pad)
#define B_STRIDE 136             // u32 per B k2-row
#define A_U32    (128 * A_STRIDE)          // 4608
#define B_U32    (32 * B_STRIDE)           // 4352
#define STAGE_U32 (A_U32 + B_U32)          // 8960
#define GEMM_SMEM (3 * STAGE_U32 * 4)      // 107520 B

__global__ __launch_bounds__(128, 2)
void gemm_h(const __half* __restrict__ A, const __half2* __restrict__ Wp,
            __half* __restrict__ C, int M, int K, int nChunk) {
    extern __shared__ uint32_t sm[];
    uint32_t smb;
    asm("{ .reg .u64 t; cvta.to.shared.u64 t, %1; cvt.u32.u64 %0, t; }"
        : "=r"(smb) : "l"(sm));

    const int tid  = threadIdx.x;
    const int lane = tid & 31;
    const int warp = tid >> 5;
    const int wm   = (warp & 1) * 64;
    const int wn   = (warp >> 1) * 64;
    const int grp  = lane >> 2;
    const int thr  = lane & 3;

    // ldmatrix per-lane addressing: lane j of each 8-lane group supplies the
    // row address of one 8x8 matrix.  sel 0: rows +0 @k+0 | 1: rows +8 @k+0
    // | 2: rows +0 @k+8 | 3: rows +8 @k+8  ->  regs a0,a1,a2,a3.
    const int lj   = lane & 7;
    const int sel  = lane >> 3;
    const int rofs = lj + (sel & 1) * 8;        // row within the 16-row tile
    const int cofs = (sel >> 1) * 4;            // u32 offset within k16 (0|4)

    const int rowBase = blockIdx.y * 128;
    const int colBase = blockIdx.x * 128;

    auto issue = [&](int chunk, int st) {
        const uint32_t base = smb + (uint32_t)st * (STAGE_U32 * 4);
        const int k0  = chunk * 64;       // halves
        const int k02 = chunk * 32;       // half2 rows of Wp
#pragma unroll
        for (int u = 0; u < 8; u++) {     // A: 1024 16B chunks / 128 thr
            int t = tid + u * 128;
            int r = t >> 3, c = t & 7;
            uint32_t dst = base + (uint32_t)(r * A_STRIDE + c * 4) * 4u;
            int row = rowBase + r;
            int ok  = row < M;
            const __half* srcp = A + (size_t)(ok ? row : 0) * K + k0 + c * 8;
            CP_ASYNC16(dst, srcp, ok ? 16 : 0);
        }
#pragma unroll
        for (int u = 0; u < 8; u++) {     // B: 1024 16B chunks / 128 thr
            int t = tid + u * 128;
            int k2 = t >> 5, c = t & 31;
            uint32_t dst = base + (uint32_t)(A_U32 + k2 * B_STRIDE + c * 4) * 4u;
            const __half2* srcp = Wp + (size_t)(k02 + k2) * NH + colBase + c * 4;
            CP_ASYNC16(dst, srcp, 16);
        }
    };

    float acc[4][8][4];
#pragma unroll
    for (int i = 0; i < 4; i++)
#pragma unroll
        for (int j = 0; j < 8; j++)
#pragma unroll
            for (int r = 0; r < 4; r++) acc[i][j][r] = 0.f;

    issue(0, 0); CP_COMMIT();
    issue(1, 1); CP_COMMIT();

    for (int i = 0; i < nChunk; i++) {
        const int si = i % 3;
        CP_WAIT(1);
        __syncthreads();

        const uint32_t stageB = smb + (uint32_t)si * (STAGE_U32 * 4);
        const uint32_t* Bs = sm + si * STAGE_U32 + A_U32;

#pragma unroll
        for (int kk = 0; kk < 4; kk++) {       // four k16 groups per chunk
            const int kb2 = kk * 8;            // u32 (half2) offset
            uint32_t af[4][4], bf[8][2];
#pragma unroll
            for (int mi = 0; mi < 4; mi++) {
                uint32_t addr = stageB +
                    (uint32_t)((wm + mi * 16 + rofs) * A_STRIDE + kb2 + cofs) * 4u;
                LDSM_X4(af[mi][0], af[mi][1], af[mi][2], af[mi][3], addr);
            }
#pragma unroll
            for (int ni = 0; ni < 8; ni++) {
                int n = wn + ni * 8 + grp;
                bf[ni][0] = Bs[(kb2 + thr) * B_STRIDE + n];
                bf[ni][1] = Bs[(kb2 + 4 + thr) * B_STRIDE + n];
            }
#pragma unroll
            for (int mi = 0; mi < 4; mi++)
#pragma unroll
                for (int ni = 0; ni < 8; ni++)
                    mma_f16(acc[mi][ni], af[mi], bf[ni]);
        }

        if (i + 2 < nChunk) { issue(i + 2, (i + 2) % 3); CP_COMMIT(); }
    }

    // epilogue: fp32 acc -> fp16 store
#pragma unroll
    for (int mi = 0; mi < 4; mi++) {
        int m0 = rowBase + wm + mi * 16 + grp;
        int m1 = m0 + 8;
#pragma unroll
        for (int ni = 0; ni < 8; ni++) {
            int n0 = colBase + wn + ni * 8 + thr * 2;
            if (m0 < M) {
                __half2 h = __floats2half2_rn(acc[mi][ni][0], acc[mi][ni][1]);
                *(__half2*)&C[(size_t)m0 * NH + n0] = h;
            }
            if (m1 < M) {
                __half2 h = __floats2half2_rn(acc[mi][ni][2], acc[mi][ni][3]);
                *(__half2*)&C[(size_t)m1 * NH + n0] = h;
            }
        }
    }
}

// ---------------- conversions ---------------------------------------------------
__global__ void k_halfx(const float* __restrict__ x, __half* __restrict__ xh,
                        int total4) {
    int i = blockIdx.x * blockDim.x + threadIdx.x;
    if (i < total4) {
        float4 v = ((const float4*)x)[i];
        __half2 h0 = __floats2half2_rn(v.x, v.y);
        __half2 h1 = __floats2half2_rn(v.z, v.w);
        ((__half2*)xh)[2 * i]     = h0;
        ((__half2*)xh)[2 * i + 1] = h1;
    }
}

__global__ void k_packW(const float* __restrict__ W, __half2* __restrict__ Wp,
                        int k2total) {
    int i = blockIdx.x * blockDim.x + threadIdx.x;
    if (i < k2total * NH) {
        int k2 = i >> 10, n = i & 1023;
        float a = W[(size_t)(2 * k2) * NH + n];
        float b = W[(size_t)(2 * k2 + 1) * NH + n];
        Wp[i] = __floats2half2_rn(a, b);
    }
}

// ---------------- CSR build ----------------------------------------------------
__global__ void k_zero_all(int* cnti, int* cur, float* pooled, float* cntg) {
    int i = blockIdx.x * blockDim.x + threadIdx.x;
    if (i < NNODE) { cnti[i] = 0; cur[i] = 0; }
    if (i < NG * NH) pooled[i] = 0.f;
    if (i < NG) cntg[i] = 0.f;
}

__global__ void k_count_i(const int* __restrict__ dst, int* cnti) {
    int e = blockIdx.x * blockDim.x + threadIdx.x;
    if (e < NEDGE) atomicAdd(&cnti[dst[e]], 1);
}

__global__ void k_dis(const int* __restrict__ cnti, float* dis, float* selfw) {
    int n = blockIdx.x * blockDim.x + threadIdx.x;
    if (n < NNODE) {
        float d = 1.0f + (float)cnti[n];
        dis[n]   = rsqrtf(d);
        selfw[n] = 1.0f / d;
    }
}

__global__ __launch_bounds__(256)
void k_scan1(const int* __restrict__ cnti, int* base, int* bsum) {
    __shared__ int s[256];
    int n = blockIdx.x * 256 + threadIdx.x;
    int v = (n < NNODE) ? cnti[n] : 0;
    s[threadIdx.x] = v;
    __syncthreads();
#pragma unroll
    for (int o = 1; o < 256; o <<= 1) {
        int t = (threadIdx.x >= o) ? s[threadIdx.x - o] : 0;
        __syncthreads();
        s[threadIdx.x] += t;
        __syncthreads();
    }
    if (n < NNODE) base[n] = s[threadIdx.x] - v;
    if (threadIdx.x == 255) bsum[blockIdx.x] = s[255];
}

__global__ __launch_bounds__(256)
void k_scan2(int* bsum) {
    __shared__ int s[256];
    int v = (threadIdx.x < NSCANB) ? bsum[threadIdx.x] : 0;
    s[threadIdx.x] = v;
    __syncthreads();
#pragma unroll
    for (int o = 1; o < 256; o <<= 1) {
        int t = (threadIdx.x >= o) ? s[threadIdx.x - o] : 0;
        __syncthreads();
        s[threadIdx.x] += t;
        __syncthreads();
    }
    if (threadIdx.x < NSCANB) bsum[threadIdx.x] = s[threadIdx.x] - v;
}

__global__ void k_scan3(int* base, const int* __restrict__ bsum) {
    int n = blockIdx.x * 256 + threadIdx.x;
    if (n < NNODE) base[n] += bsum[blockIdx.x];
    if (n == 0) base[NNODE] = NEDGE;
}

__global__ void k_fill(const int* __restrict__ src, const int* __restrict__ dst,
                       const float* __restrict__ dis, const int* __restrict__ base,
                       int* cur, int* csrs, float* csrw) {
    int e = blockIdx.x * blockDim.x + threadIdx.x;
    if (e < NEDGE) {
        int d = dst[e], s = src[e];
        int pos = base[d] + atomicAdd(&cur[d], 1);
        csrs[pos] = s;
        csrw[pos] = dis[s] * dis[d];
    }
}

// ---------------- fp16 gather (CSR), edge loop unrolled x4 ---------------------
__device__ __forceinline__ float4 ld_h4(const __half* row, int t) {
    uint2 q = ((const uint2*)row)[t];
    __half2 h0 = *reinterpret_cast<__half2*>(&q.x);
    __half2 h1 = *reinterpret_cast<__half2*>(&q.y);
    float2 f0 = __half22float2(h0);
    float2 f1 = __half22float2(h1);
    return make_float4(f0.x, f0.y, f1.x, f1.y);
}

__device__ __forceinline__ float4 gather_row(const __half* __restrict__ in,
                                             const int* __restrict__ csrs,
                                             const float* __restrict__ csrw,
                                             int n, int b0, int b1, float s, int t) {
    float4 v = ld_h4(in + (size_t)n * NH, t);
    float4 acc = make_float4(v.x * s, v.y * s, v.z * s, v.w * s);
    int j = b0;
    for (; j + 4 <= b1; j += 4) {
        int   s0 = csrs[j],     s1 = csrs[j + 1];
        int   s2 = csrs[j + 2], s3 = csrs[j + 3];
        float w0 = csrw[j],     w1 = csrw[j + 1];
        float w2 = csrw[j + 2], w3 = csrw[j + 3];
        float4 u0 = ld_h4(in + (size_t)s0 * NH, t);
        float4 u1 = ld_h4(in + (size_t)s1 * NH, t);
        float4 u2 = ld_h4(in + (size_t)s2 * NH, t);
        float4 u3 = ld_h4(in + (size_t)s3 * NH, t);
        acc.x += u0.x * w0 + u1.x * w1 + u2.x * w2 + u3.x * w3;
        acc.y += u0.y * w0 + u1.y * w1 + u2.y * w2 + u3.y * w3;
        acc.z += u0.z * w0 + u1.z * w1 + u2.z * w2 + u3.z * w3;
        acc.w += u0.w * w0 + u1.w * w1 + u2.w * w2 + u3.w * w3;
    }
    if (j + 2 <= b1) {
        int   s0 = csrs[j],   s1 = csrs[j + 1];
        float w0 = csrw[j],   w1 = csrw[j + 1];
        float4 u0 = ld_h4(in + (size_t)s0 * NH, t);
        float4 u1 = ld_h4(in + (size_t)s1 * NH, t);
        acc.x += u0.x * w0 + u1.x * w1;
        acc.y += u0.y * w0 + u1.y * w1;
        acc.z += u0.z * w0 + u1.z * w1;
        acc.w += u0.w * w0 + u1.w * w1;
        j += 2;
    }
    if (j < b1) {
        float4 u0 = ld_h4(in + (size_t)csrs[j] * NH, t);
        float w0 = csrw[j];
        acc.x += u0.x * w0; acc.y += u0.y * w0;
        acc.z += u0.z * w0; acc.w += u0.w * w0;
    }
    return acc;
}

__global__ __launch_bounds__(256)
void k_gather_relu_h(const __half* __restrict__ in, __half* __restrict__ out,
                     const int* __restrict__ csrs, const float* __restrict__ csrw,
                     const int* __restrict__ base, const float* __restrict__ selfw,
                     const float* __restrict__ bias) {
    int n = blockIdx.x;
    int t = threadIdx.x;
    float4 acc = gather_row(in, csrs, csrw, n, base[n], base[n + 1], selfw[n], t);
    int h = t * 4;
    acc.x = fmaxf(acc.x + bias[h + 0], 0.f);
    acc.y = fmaxf(acc.y + bias[h + 1], 0.f);
    acc.z = fmaxf(acc.z + bias[h + 2], 0.f);
    acc.w = fmaxf(acc.w + bias[h + 3], 0.f);
    __half2 o0 = __floats2half2_rn(acc.x, acc.y);
    __half2 o1 = __floats2half2_rn(acc.z, acc.w);
    uint2 q;
    q.x = *reinterpret_cast<uint32_t*>(&o0);
    q.y = *reinterpret_cast<uint32_t*>(&o1);
    ((uint2*)(out + (size_t)n * NH))[t] = q;
}

__global__ __launch_bounds__(256)
void k_gather_pool_h(const __half* __restrict__ in, const int* __restrict__ batch,
                     const int* __restrict__ csrs, const float* __restrict__ csrw,
                     const int* __restrict__ base, const float* __restrict__ selfw,
                     const float* __restrict__ bias, float* __restrict__ pooled,
                     float* __restrict__ cntg) {
    int n = blockIdx.x;
    int t = threadIdx.x;
    float4 acc = gather_row(in, csrs, csrw, n, base[n], base[n + 1], selfw[n], t);
    int h = t * 4;
    acc.x = fmaxf(acc.x + bias[h + 0], 0.f);
    acc.y = fmaxf(acc.y + bias[h + 1], 0.f);
    acc.z = fmaxf(acc.z + bias[h + 2], 0.f);
    acc.w = fmaxf(acc.w + bias[h + 3], 0.f);
    int g = batch[n];
    red_add_v4(pooled + (size_t)g * NH + h, acc);
    if (t == 0) atomicAdd(&cntg[g], 1.0f);
}

// ---------------- head ---------------------------------------------------------
__global__ void k_comb(const float* __restrict__ gx, const float* __restrict__ pooled,
                       const float* __restrict__ cntg, float* __restrict__ comb) {
    int g = blockIdx.y;
    int i = blockIdx.x * blockDim.x + threadIdx.x;
    float v;
    if (i < NF) v = gx[(size_t)g * NF + i];
    else        v = pooled[(size_t)g * NH + (i - NF)] / fmaxf(cntg[g], 1.0f);
    comb[(size_t)g * NCOMB + i] = v;
}

__global__ __launch_bounds__(256)
void k_mlp1(const float* __restrict__ comb, const float* __restrict__ fw1,
            const float* __restrict__ fb1, float* __restrict__ hid) {
    __shared__ float sc[32][65];
    int j  = blockIdx.x * 16 + (threadIdx.x & 15);
    int gq = threadIdx.x >> 4;
    float acc[4] = {0.f, 0.f, 0.f, 0.f};
    for (int kb = 0; kb < NCOMB; kb += 32) {
#pragma unroll
        for (int u = 0; u < 8; u++) {
            int l = threadIdx.x + 256 * u;
            int g = l >> 5, kk = l & 31;
            sc[kk][g] = comb[(size_t)g * NCOMB + kb + kk];
        }
        __syncthreads();
#pragma unroll 8
        for (int kk = 0; kk < 32; kk++) {
            float w = fw1[(size_t)(kb + kk) * NFUSE + j];
#pragma unroll
            for (int q = 0; q < 4; q++) acc[q] += sc[kk][gq * 4 + q] * w;
        }
        __syncthreads();
    }
#pragma unroll
    for (int q = 0; q < 4; q++) {
        int g = gq * 4 + q;
        hid[(size_t)g * NFUSE + j] = fmaxf(acc[q] + fb1[j], 0.f);
    }
}

__global__ __launch_bounds__(128)
void k_mlp2(const float* __restrict__ hid, const float* __restrict__ fw2,
            const float* __restrict__ fb2, float* __restrict__ out) {
    __shared__ float sh[NFUSE];
    int g = blockIdx.x;
    for (int i = threadIdx.x; i < NFUSE; i += blockDim.x)
        sh[i] = hid[(size_t)g * NFUSE + i];
    __syncthreads();
    int c = threadIdx.x;
    if (c < NC) {
        float acc = 0.f;
#pragma unroll 4
        for (int k = 0; k < NFUSE; k++) acc += sh[k] * fw2[(size_t)k * NC + c];
        out[(size_t)g * NC + c] = acc + fb2[c];
    }
}

// ---------------- launch --------------------------------------------------------
extern "C" void kernel_launch(void* const* d_in, const int* in_sizes, int n_in,
                              void* d_out, int out_size) {
    const float* gx    = (const float*)d_in[0];
    const float* x     = (const float*)d_in[1];
    const int*   eidx  = (const int*)  d_in[2];
    const int*   batch = (const int*)  d_in[3];
    const float* W1    = (const float*)d_in[4];
    const float* b1    = (const float*)d_in[5];
    const float* W2    = (const float*)d_in[6];
    const float* b2    = (const float*)d_in[7];
    const float* fw1   = (const float*)d_in[8];
    const float* fb1   = (const float*)d_in[9];
    const float* fw2   = (const float*)d_in[10];
    const float* fb2   = (const float*)d_in[11];
    float* out = (float*)d_out;

    const int* src = eidx;
    const int* dst = eidx + NEDGE;

    __half *xh, *b1h, *b2h;
    __half2 *wp1, *wp2;
    float *dis, *selfw, *csrw, *pooled, *cntg, *comb, *hid;
    int *cnti, *cur, *basev, *bsum, *csrs;
    cudaGetSymbolAddress((void**)&xh,     g_xh);
    cudaGetSymbolAddress((void**)&b1h,    g_b1h);
    cudaGetSymbolAddress((void**)&b2h,    g_b2h);
    cudaGetSymbolAddress((void**)&wp1,    g_wp1);
    cudaGetSymbolAddress((void**)&wp2,    g_wp2);
    cudaGetSymbolAddress((void**)&dis,    g_dis);
    cudaGetSymbolAddress((void**)&selfw,  g_selfw);
    cudaGetSymbolAddress((void**)&cnti,   g_cnti);
    cudaGetSymbolAddress((void**)&cur,    g_cur);
    cudaGetSymbolAddress((void**)&basev,  g_basev);
    cudaGetSymbolAddress((void**)&bsum,   g_bsum);
    cudaGetSymbolAddress((void**)&csrs,   g_csrs);
    cudaGetSymbolAddress((void**)&csrw,   g_csrw);
    cudaGetSymbolAddress((void**)&pooled, g_pooled);
    cudaGetSymbolAddress((void**)&cntg,   g_cntg);
    cudaGetSymbolAddress((void**)&comb,   g_comb);
    cudaGetSymbolAddress((void**)&hid,    g_hid);

    cudaFuncSetAttribute(gemm_h, cudaFuncAttributeMaxDynamicSharedMemorySize,
                         GEMM_SMEM);

    const int TPB = 256;
    const int edgeBlocks = (NEDGE + TPB - 1) / TPB;
    const int zb = ((NNODE > NG * NH ? NNODE : NG * NH) + TPB - 1) / TPB;

    dim3 gg(NH / 128, (NNODE + 127) / 128);   // (8, 391)

    // R14 launch structure; gemm1 at slot 4 (ncu capture window)
    k_halfx <<<(NNODE * NF / 4 + TPB - 1) / TPB, TPB>>>(x, xh, NNODE * NF / 4); // 1
    k_packW <<<((NF / 2) * NH + TPB - 1) / TPB, TPB>>>(W1, wp1, NF / 2);        // 2
    k_zero_all<<<zb, TPB>>>(cnti, cur, pooled, cntg);                           // 3
    gemm_h  <<<gg, 128, GEMM_SMEM>>>(xh, wp1, b1h, NNODE, NF, NF / 64);         // 4
    k_count_i<<<edgeBlocks, TPB>>>(dst, cnti);                                  // 5
    k_dis   <<<NSCANB, TPB>>>(cnti, dis, selfw);                                // 6
    k_scan1 <<<NSCANB, TPB>>>(cnti, basev, bsum);                               // 7
    k_scan2 <<<1, TPB>>>(bsum);                                                 // 8
    k_scan3 <<<NSCANB, TPB>>>(basev, bsum);                                     // 9
    k_fill  <<<edgeBlocks, TPB>>>(src, dst, dis, basev, cur, csrs, csrw);       // 10
    k_gather_relu_h<<<NNODE, 256>>>(b1h, b2h, csrs, csrw, basev, selfw, b1);    // 11

    k_packW <<<((NH / 2) * NH + TPB - 1) / TPB, TPB>>>(W2, wp2, NH / 2);        // 12
    gemm_h  <<<gg, 128, GEMM_SMEM>>>(b2h, wp2, b1h, NNODE, NH, NH / 64);        // 13
    k_gather_pool_h<<<NNODE, 256>>>(b1h, batch, csrs, csrw, basev, selfw, b2,
                                    pooled, cntg);                              // 14

    dim3 gc(NCOMB / TPB, NG);
    k_comb<<<gc, TPB>>>(gx, pooled, cntg, comb);                                // 15
    k_mlp1<<<NFUSE / 16, 256>>>(comb, fw1, fb1, hid);                           // 16
    k_mlp2<<<NG, 128>>>(hid, fw2, fb2, out);                                    // 17
}